// round 3
// baseline (speedup 1.0000x reference)
#include <cuda_runtime.h>
#include <cuda_bf16.h>
#include <math_constants.h>

#define N_NODES   262144
#define D_IN      512
#define B_GRAPHS  256
#define GATES     2048      // 4*D_IN
#define K_COMB    1024      // combined K (h:512 | r:512)
#define STEPS     6

// ----------------- device scratch (no runtime allocation allowed) -----------
__device__ __align__(16) float g_W[GATES * K_COMB];     // combined weights [2048][1024]
__device__ __align__(16) float g_bias[GATES];           // b_ih + b_hh
__device__ __align__(16) float g_hr[B_GRAPHS * 1024];   // [h | r] = q_star layout
__device__ __align__(16) float g_c[B_GRAPHS * D_IN];
__device__ __align__(16) float g_gates[B_GRAPHS * GATES];
__device__ int   g_off[B_GRAPHS + 1];

// ----------------------------- helpers --------------------------------------
__device__ __forceinline__ float sigm(float v) {
    return 1.0f / (1.0f + __expf(-v));
}

// --------------------------- prep kernels -----------------------------------
__global__ void prep_w_kernel(const float* __restrict__ w_ih,
                              const float* __restrict__ w_hh,
                              const float* __restrict__ b_ih,
                              const float* __restrict__ b_hh) {
    int idx = blockIdx.x * blockDim.x + threadIdx.x;   // 0 .. 2048*1024-1
    int n = idx >> 10;
    int k = idx & 1023;
    float v = w_ih[n * 1024 + k];
    if (k < 512) v += w_hh[n * 512 + k];
    g_W[idx] = v;
    if (idx < GATES) g_bias[idx] = b_ih[idx] + b_hh[idx];
}

// batch is int32, sorted ascending in [0, B).
// g_off[t] = lower_bound(batch, t)  — bounded binary search, no races.
__global__ void offsets_kernel(const int* __restrict__ batch) {
    int t = blockIdx.x * blockDim.x + threadIdx.x;
    if (t > B_GRAPHS) return;
    int lo = 0, hi = N_NODES;
    while (lo < hi) {
        int mid = (lo + hi) >> 1;
        if (batch[mid] < t) lo = mid + 1; else hi = mid;
    }
    g_off[t] = lo;
}

// Step 0: q_star = 0, h = 0  ->  gates = bias (identical for every graph)
__global__ void lstm_init_kernel() {
    int b = blockIdx.x;          // 256
    int d = threadIdx.x;         // 512
    float i = sigm(g_bias[d]);
    float g = tanhf(g_bias[1024 + d]);
    float o = sigm(g_bias[1536 + d]);
    float c = i * g;
    g_c[b * D_IN + d]  = c;
    g_hr[b * 1024 + d] = o * tanhf(c);
}

// --------------------------- GEMM: gates = hr @ W^T + bias -------------------
// M=256, N=2048, K=1024.  64x64 tiles, 256 threads, 4x4 micro-tile.
#define GBM 64
#define GBN 64
#define GBK 16

__global__ void __launch_bounds__(256) gemm_kernel() {
    __shared__ __align__(16) float As[GBK][GBM + 4];
    __shared__ __align__(16) float Ws[GBK][GBN + 4];

    const int bm = blockIdx.y * GBM;       // gridDim.y = 4
    const int bn = blockIdx.x * GBN;       // gridDim.x = 32
    const int tid = threadIdx.x;
    const int tx = tid & 15;
    const int ty = tid >> 4;

    const int lr = tid >> 2;               // 0..63 row within tile
    const int lc = (tid & 3) * 4;          // k offset 0,4,8,12

    const float* Ag = g_hr + (bm + lr) * K_COMB + lc;
    const float* Wg = g_W  + (bn + lr) * K_COMB + lc;

    float acc[4][4];
    #pragma unroll
    for (int i = 0; i < 4; i++)
        #pragma unroll
        for (int j = 0; j < 4; j++) acc[i][j] = 0.0f;

    float4 av = *(const float4*)(Ag);
    float4 wv = *(const float4*)(Wg);

    for (int k0 = 0; k0 < K_COMB; k0 += GBK) {
        __syncthreads();
        As[lc + 0][lr] = av.x; As[lc + 1][lr] = av.y;
        As[lc + 2][lr] = av.z; As[lc + 3][lr] = av.w;
        Ws[lc + 0][lr] = wv.x; Ws[lc + 1][lr] = wv.y;
        Ws[lc + 2][lr] = wv.z; Ws[lc + 3][lr] = wv.w;
        __syncthreads();

        if (k0 + GBK < K_COMB) {
            av = *(const float4*)(Ag + k0 + GBK);
            wv = *(const float4*)(Wg + k0 + GBK);
        }

        #pragma unroll
        for (int k = 0; k < GBK; k++) {
            float4 a4 = *(const float4*)&As[k][ty * 4];
            float4 w4 = *(const float4*)&Ws[k][tx * 4];
            float a[4] = {a4.x, a4.y, a4.z, a4.w};
            float w[4] = {w4.x, w4.y, w4.z, w4.w};
            #pragma unroll
            for (int i = 0; i < 4; i++)
                #pragma unroll
                for (int j = 0; j < 4; j++)
                    acc[i][j] = fmaf(a[i], w[j], acc[i][j]);
        }
    }

    #pragma unroll
    for (int i = 0; i < 4; i++) {
        int row = bm + ty * 4 + i;
        #pragma unroll
        for (int j = 0; j < 4; j++) {
            int col = bn + tx * 4 + j;
            g_gates[row * GATES + col] = acc[i][j] + g_bias[col];
        }
    }
}

// --------------------------- LSTM pointwise ----------------------------------
__global__ void lstm_pw_kernel() {
    int idx = blockIdx.x * blockDim.x + threadIdx.x;   // 0 .. 131071
    int b = idx >> 9;
    int d = idx & 511;
    const float* gr = g_gates + b * GATES + d;
    float i = sigm(gr[0]);
    float f = sigm(gr[512]);
    float g = tanhf(gr[1024]);
    float o = sigm(gr[1536]);
    float c = f * g_c[idx] + i * g;
    g_c[idx] = c;
    g_hr[b * 1024 + d] = o * tanhf(c);     // q = h into hr[:, :512]
}

// --------------------------- fused attention (single pass) -------------------
// One block per graph. 16 warps; each warp: one node at a time, online softmax
// with register-resident r[512] (16 floats/lane). Merge partials in smem.
// Register layout convention (both xv and qv): slot j*4+c  <->  x-column
// 128*j + 4*lane + c.
__global__ void __launch_bounds__(512, 2) attn_kernel(const float* __restrict__ x) {
    const int b    = blockIdx.x;
    const int tid  = threadIdx.x;
    const int wid  = tid >> 5;
    const int lane = tid & 31;

    const int s0 = g_off[b];
    const int s1 = g_off[b + 1];

    // q = hr[b, 0:512] loaded with the SAME float4 layout as xv
    const float4* q4 = (const float4*)(g_hr + b * 1024);
    float qv[16];
    #pragma unroll
    for (int j = 0; j < 4; j++) {
        float4 v = q4[j * 32 + lane];
        qv[j * 4 + 0] = v.x; qv[j * 4 + 1] = v.y;
        qv[j * 4 + 2] = v.z; qv[j * 4 + 3] = v.w;
    }

    float m = -CUDART_INF_F;
    float denom = 0.0f;
    float r[16];
    #pragma unroll
    for (int k = 0; k < 16; k++) r[k] = 0.0f;

    for (int n = s0 + wid; n < s1; n += 16) {
        const float4* xr = (const float4*)(x + (size_t)n * D_IN);
        float xv[16];
        #pragma unroll
        for (int j = 0; j < 4; j++) {
            float4 v = xr[j * 32 + lane];
            xv[j * 4 + 0] = v.x; xv[j * 4 + 1] = v.y;
            xv[j * 4 + 2] = v.z; xv[j * 4 + 3] = v.w;
        }

        float p = 0.0f;
        #pragma unroll
        for (int j = 0; j < 16; j++) p = fmaf(xv[j], qv[j], p);
        #pragma unroll
        for (int o = 16; o; o >>= 1) p += __shfl_xor_sync(0xffffffffu, p, o);
        const float e = p;

        // branchless online softmax update
        const float mn = fmaxf(m, e);
        const float sc = __expf(m - mn);   // first iter: exp(-inf) = 0
        const float w  = __expf(e - mn);
        denom = fmaf(denom, sc, w);
        #pragma unroll
        for (int k = 0; k < 16; k++) r[k] = fmaf(r[k], sc, w * xv[k]);
        m = mn;
    }

    // ---- merge 16 warp partials ----
    __shared__ __align__(16) float  sm_m[16];
    __shared__ __align__(16) float  sm_d[16];
    __shared__ __align__(16) float  sm_scale[16];
    __shared__ __align__(16) float4 sm_r[16][128];   // 16 x 512 floats = 32 KB

    if (lane == 0) { sm_m[wid] = m; sm_d[wid] = denom; }
    #pragma unroll
    for (int j = 0; j < 4; j++)
        sm_r[wid][j * 32 + lane] = make_float4(r[j*4+0], r[j*4+1], r[j*4+2], r[j*4+3]);
    __syncthreads();

    float M = -CUDART_INF_F;
    #pragma unroll
    for (int w = 0; w < 16; w++) M = fmaxf(M, sm_m[w]);
    if (tid < 16)
        sm_scale[tid] = (sm_m[tid] == -CUDART_INF_F) ? 0.0f : __expf(sm_m[tid] - M);
    __syncthreads();

    float Dn = 0.0f;
    #pragma unroll
    for (int w = 0; w < 16; w++) Dn += sm_d[w] * sm_scale[w];
    const float inv = 1.0f / (Dn + 1e-16f);

    // float index i of a 512-float partial row maps to x-column i (identity):
    // 4*(j*32+lane)+c = 128j+4lane+c. So column tid sums scaled partials.
    float acc = 0.0f;
    #pragma unroll
    for (int w = 0; w < 16; w++)
        acc = fmaf(((const float*)sm_r[w])[tid], sm_scale[w], acc);
    g_hr[b * 1024 + 512 + tid] = acc * inv;
}

// ------------------------------- output --------------------------------------
__global__ void copyout_kernel(float* __restrict__ out) {
    int idx = blockIdx.x * blockDim.x + threadIdx.x;   // 0 .. 262143
    out[idx] = g_hr[idx];
}

// ------------------------------- launch --------------------------------------
extern "C" void kernel_launch(void* const* d_in, const int* in_sizes, int n_in,
                              void* d_out, int out_size) {
    const float* x     = (const float*)d_in[0];
    const int*   batch = (const int*)d_in[1];
    const float* w_ih  = (const float*)d_in[2];
    const float* w_hh  = (const float*)d_in[3];
    const float* b_ih  = (const float*)d_in[4];
    const float* b_hh  = (const float*)d_in[5];
    float* out = (float*)d_out;

    prep_w_kernel<<<(GATES * K_COMB) / 256, 256>>>(w_ih, w_hh, b_ih, b_hh);
    offsets_kernel<<<2, 160>>>(batch);
    lstm_init_kernel<<<B_GRAPHS, 512>>>();

    for (int s = 0; s < STEPS; s++) {
        if (s > 0) {
            gemm_kernel<<<dim3(32, 4), 256>>>();
            lstm_pw_kernel<<<(B_GRAPHS * D_IN) / 512, 512>>>();
        }
        attn_kernel<<<B_GRAPHS, 512>>>(x);
    }
    copyout_kernel<<<(B_GRAPHS * 1024) / 256, 256>>>(out);
}